// round 5
// baseline (speedup 1.0000x reference)
#include <cuda_runtime.h>

#define NT 512
typedef unsigned long long ull;

// ---------- packed f32x2 helpers (Blackwell sm_103a) ----------
__device__ __forceinline__ ull pk(float lo, float hi) {
    ull r; asm("mov.b64 %0,{%1,%2};" : "=l"(r) : "f"(lo), "f"(hi)); return r;
}
__device__ __forceinline__ float2 upk(ull v) {
    float2 f; asm("mov.b64 {%0,%1},%2;" : "=f"(f.x), "=f"(f.y) : "l"(v)); return f;
}
__device__ __forceinline__ ull fma2(ull a, ull b, ull c) {
    ull d; asm("fma.rn.f32x2 %0,%1,%2,%3;" : "=l"(d) : "l"(a), "l"(b), "l"(c)); return d;
}

// smem layout (floats)
#define OFF_XWT 0            // [256][68]  xwT[c][row]
#define OFF_QT  17408        // [64][68]   qT[d_local][i]   (2 heads)
#define OFF_KT  21760        // [64][68]
#define OFF_VB  26112        // [64][64]   vb[j][d_local]
#define OFF_P2  30208        // [2][64][68]
#define OFF_OBT 38912        // [256][68]  obT[c][i]
#define SMEM_FLOATS 56320    // 225,280 bytes

__global__ void __launch_bounds__(NT, 1)
local_attn_kernel(const float* __restrict__ x,
                  const float* __restrict__ Wq,
                  const float* __restrict__ Wkv,
                  const float* __restrict__ pos,
                  const float* __restrict__ Wp,
                  const float* __restrict__ bp,
                  float* __restrict__ out)
{
    extern __shared__ float sm[];
    float* xwT = sm + OFF_XWT;
    float* qT  = sm + OFF_QT;
    float* kT  = sm + OFF_KT;
    float* vb  = sm + OFF_VB;
    float* P2  = sm + OFF_P2;
    float* obT = sm + OFF_OBT;

    const int t   = threadIdx.x;
    const int wid = blockIdx.x;
    const int b  = wid >> 10;
    const int nh = (wid >> 5) & 31;
    const int nw = wid & 31;

    const float* xbase = x + (((b * 256 + nh * 8) * 256 + nw * 8) << 8);

    // ---------------- Phase A: load + transpose window into xwT[c][row] ----------------
    {
        const int c  = t & 255;
        const int r0 = t >> 8;           // 0,1
        #pragma unroll
        for (int rep = 0; rep < 32; ++rep) {
            int row = r0 + rep * 2;
            int i = row >> 3, j = row & 7;
            float v = __ldg(xbase + i * 65536 + j * 256 + c);
            xwT[c * 68 + row] = v;
        }
    }
    __syncthreads();

    // thread mappings
    const int rg = t >> 6;      // 0..7  (QKV / proj row group: rows rg*8..rg*8+7)
    const int cg = t & 63;      // 0..63 (QKV / proj col)
    const int sh   = t >> 8;        // 0/1 head-local (sim/av)
    const int sidx = t & 255;
    const int sig  = sidx >> 3;     // 0..31 (sim: rows sig*2, sig*2+1)
    const int sjg  = sidx & 7;      // 0..7  (sim: cols sjg*8..+7)
    const int aig  = sidx >> 2;     // 0..63 (av: row)
    const int adg  = sidx & 3;      // 0..3  (av: cols adg*8..+7)

    const float qscale = 0.17677669529663687f;

    for (int hb = 0; hb < 4; ++hb) {
        // ---------------- QKV: C[64 x 192] = xw @ [Wq|Wk|Wv] (2 heads) ----------------
        {
            ull aq[4], ak[4], avv[4];
            #pragma unroll
            for (int i = 0; i < 4; ++i) { aq[i] = 0ULL; ak[i] = 0ULL; avv[i] = 0ULL; }
            const float* wqp = Wq  + hb * 64 + cg;
            const float* wkp = Wkv + hb * 64 + cg;
            const float* wvp = Wkv + 256 + hb * 64 + cg;
            const float* xp  = xwT + rg * 8;
            #pragma unroll 4
            for (int c = 0; c < 256; ++c) {
                float wq = __ldg(wqp + c * 256);
                float wk = __ldg(wkp + c * 512);
                float wv = __ldg(wvp + c * 512);
                ull bq = pk(wq, wq), bk = pk(wk, wk), bv = pk(wv, wv);
                ulonglong2 xa = *(const ulonglong2*)(xp + c * 68);
                ulonglong2 xb = *(const ulonglong2*)(xp + c * 68 + 4);
                aq[0] = fma2(xa.x, bq, aq[0]);  ak[0] = fma2(xa.x, bk, ak[0]);  avv[0] = fma2(xa.x, bv, avv[0]);
                aq[1] = fma2(xa.y, bq, aq[1]);  ak[1] = fma2(xa.y, bk, ak[1]);  avv[1] = fma2(xa.y, bv, avv[1]);
                aq[2] = fma2(xb.x, bq, aq[2]);  ak[2] = fma2(xb.x, bk, ak[2]);  avv[2] = fma2(xb.x, bv, avv[2]);
                aq[3] = fma2(xb.y, bq, aq[3]);  ak[3] = fma2(xb.y, bk, ak[3]);  avv[3] = fma2(xb.y, bv, avv[3]);
            }
            #pragma unroll
            for (int p = 0; p < 4; ++p) {
                float2 fq = upk(aq[p]);
                float2 fk = upk(ak[p]);
                float2 fv = upk(avv[p]);
                int r = rg * 8 + p * 2;
                qT[cg * 68 + r]     = fq.x * qscale;
                qT[cg * 68 + r + 1] = fq.y * qscale;
                kT[cg * 68 + r]     = fk.x;
                kT[cg * 68 + r + 1] = fk.y;
                vb[r * 64 + cg]       = fv.x;
                vb[(r + 1) * 64 + cg] = fv.y;
            }
        }
        __syncthreads();

        // ---------------- sim = q k^T + pos ; softmax ----------------
        {
            const int hq = sh * 32;
            ull s0[4], s1[4];
            #pragma unroll
            for (int i = 0; i < 4; ++i) { s0[i] = 0ULL; s1[i] = 0ULL; }
            #pragma unroll 4
            for (int d = 0; d < 32; ++d) {
                float2 qv = *(const float2*)(qT + (hq + d) * 68 + sig * 2);
                ull q0 = pk(qv.x, qv.x);
                ull q1 = pk(qv.y, qv.y);
                const float* kr = kT + (hq + d) * 68 + sjg * 8;
                ulonglong2 ka = *(const ulonglong2*)(kr);
                ulonglong2 kb = *(const ulonglong2*)(kr + 4);
                s0[0] = fma2(q0, ka.x, s0[0]);  s1[0] = fma2(q1, ka.x, s1[0]);
                s0[1] = fma2(q0, ka.y, s0[1]);  s1[1] = fma2(q1, ka.y, s1[1]);
                s0[2] = fma2(q0, kb.x, s0[2]);  s1[2] = fma2(q1, kb.x, s1[2]);
                s0[3] = fma2(q0, kb.y, s0[3]);  s1[3] = fma2(q1, kb.y, s1[3]);
            }
            const int i0 = sig * 2;
            const int hcur = hb * 2 + sh;
            const float* pp = pos + hcur * 4096 + i0 * 64 + sjg * 8;
            float sv0[8], sv1[8];
            #pragma unroll
            for (int p = 0; p < 4; ++p) {
                float2 f0 = upk(s0[p]); sv0[p * 2] = f0.x; sv0[p * 2 + 1] = f0.y;
                float2 f1 = upk(s1[p]); sv1[p * 2] = f1.x; sv1[p * 2 + 1] = f1.y;
            }
            #pragma unroll
            for (int jj = 0; jj < 8; ++jj) {
                sv0[jj] += __ldg(pp + jj);
                sv1[jj] += __ldg(pp + 64 + jj);
            }
            float m0 = sv0[0], m1 = sv1[0];
            #pragma unroll
            for (int jj = 1; jj < 8; ++jj) { m0 = fmaxf(m0, sv0[jj]); m1 = fmaxf(m1, sv1[jj]); }
            #pragma unroll
            for (int o = 1; o < 8; o <<= 1) {
                m0 = fmaxf(m0, __shfl_xor_sync(0xffffffffu, m0, o));
                m1 = fmaxf(m1, __shfl_xor_sync(0xffffffffu, m1, o));
            }
            float su0 = 0.f, su1 = 0.f;
            #pragma unroll
            for (int jj = 0; jj < 8; ++jj) {
                sv0[jj] = __expf(sv0[jj] - m0); su0 += sv0[jj];
                sv1[jj] = __expf(sv1[jj] - m1); su1 += sv1[jj];
            }
            #pragma unroll
            for (int o = 1; o < 8; o <<= 1) {
                su0 += __shfl_xor_sync(0xffffffffu, su0, o);
                su1 += __shfl_xor_sync(0xffffffffu, su1, o);
            }
            float inv0 = 1.f / su0, inv1 = 1.f / su1;
            float* pr = P2 + sh * 4352 + i0 * 68 + sjg * 8;
            *(float4*)(pr)          = make_float4(sv0[0]*inv0, sv0[1]*inv0, sv0[2]*inv0, sv0[3]*inv0);
            *(float4*)(pr + 4)      = make_float4(sv0[4]*inv0, sv0[5]*inv0, sv0[6]*inv0, sv0[7]*inv0);
            *(float4*)(pr + 68)     = make_float4(sv1[0]*inv1, sv1[1]*inv1, sv1[2]*inv1, sv1[3]*inv1);
            *(float4*)(pr + 68 + 4) = make_float4(sv1[4]*inv1, sv1[5]*inv1, sv1[6]*inv1, sv1[7]*inv1);
        }
        __syncthreads();

        // ---------------- av: out_h = P @ V ----------------
        {
            ull o[4] = {0ULL, 0ULL, 0ULL, 0ULL};
            const float* pr = P2 + sh * 4352 + aig * 68;
            const float* vp = vb + sh * 32 + adg * 8;
            #pragma unroll 4
            for (int j = 0; j < 64; ++j) {
                float p = pr[j];
                ull pb = pk(p, p);
                ulonglong2 va = *(const ulonglong2*)(vp + j * 64);
                ulonglong2 vbq = *(const ulonglong2*)(vp + j * 64 + 4);
                o[0] = fma2(pb, va.x, o[0]);
                o[1] = fma2(pb, va.y, o[1]);
                o[2] = fma2(pb, vbq.x, o[2]);
                o[3] = fma2(pb, vbq.y, o[3]);
            }
            const int dbase = (hb * 2 + sh) * 32 + adg * 8;
            #pragma unroll
            for (int p = 0; p < 4; ++p) {
                float2 f = upk(o[p]);
                obT[(dbase + p * 2) * 68 + aig]     = f.x;
                obT[(dbase + p * 2 + 1) * 68 + aig] = f.y;
            }
        }
        __syncthreads();
    }

    // ---------------- Projection: out = obT^T @ Wp + bp ----------------
    {
        ull acc[4][4];   // [col][row-pair]
        #pragma unroll
        for (int a = 0; a < 4; ++a)
            #pragma unroll
            for (int p = 0; p < 4; ++p) acc[a][p] = 0ULL;
        const float* wpp = Wp + cg * 4;
        const float* op  = obT + rg * 8;
        #pragma unroll 2
        for (int c = 0; c < 256; ++c) {
            float4 w = __ldg((const float4*)(wpp + c * 256));
            ull w0 = pk(w.x, w.x), w1 = pk(w.y, w.y), w2 = pk(w.z, w.z), w3 = pk(w.w, w.w);
            ulonglong2 xa = *(const ulonglong2*)(op + c * 68);
            ulonglong2 xb = *(const ulonglong2*)(op + c * 68 + 4);
            acc[0][0] = fma2(xa.x, w0, acc[0][0]);  acc[1][0] = fma2(xa.x, w1, acc[1][0]);
            acc[2][0] = fma2(xa.x, w2, acc[2][0]);  acc[3][0] = fma2(xa.x, w3, acc[3][0]);
            acc[0][1] = fma2(xa.y, w0, acc[0][1]);  acc[1][1] = fma2(xa.y, w1, acc[1][1]);
            acc[2][1] = fma2(xa.y, w2, acc[2][1]);  acc[3][1] = fma2(xa.y, w3, acc[3][1]);
            acc[0][2] = fma2(xb.x, w0, acc[0][2]);  acc[1][2] = fma2(xb.x, w1, acc[1][2]);
            acc[2][2] = fma2(xb.x, w2, acc[2][2]);  acc[3][2] = fma2(xb.x, w3, acc[3][2]);
            acc[0][3] = fma2(xb.y, w0, acc[0][3]);  acc[1][3] = fma2(xb.y, w1, acc[1][3]);
            acc[2][3] = fma2(xb.y, w2, acc[2][3]);  acc[3][3] = fma2(xb.y, w3, acc[3][3]);
        }
        float4 bias = __ldg((const float4*)(bp + cg * 4));
        float* obase = out + (((b * 256 + nh * 8) * 256 + nw * 8) << 8) + cg * 4;
        #pragma unroll
        for (int p = 0; p < 4; ++p) {
            float2 c0 = upk(acc[0][p]);
            float2 c1 = upk(acc[1][p]);
            float2 c2 = upk(acc[2][p]);
            float2 c3 = upk(acc[3][p]);
            int r = rg * 8 + p * 2;
            int i = r >> 3, j = r & 7;
            *(float4*)(obase + i * 65536 + j * 256) =
                make_float4(c0.x + bias.x, c1.x + bias.y, c2.x + bias.z, c3.x + bias.w);
            r = r + 1; i = r >> 3; j = r & 7;
            *(float4*)(obase + i * 65536 + j * 256) =
                make_float4(c0.y + bias.x, c1.y + bias.y, c2.y + bias.z, c3.y + bias.w);
        }
    }
}

extern "C" void kernel_launch(void* const* d_in, const int* in_sizes, int n_in,
                              void* d_out, int out_size)
{
    const float* x   = (const float*)d_in[0];
    const float* Wq  = (const float*)d_in[1];
    const float* Wkv = (const float*)d_in[2];
    const float* pos = (const float*)d_in[3];
    const float* Wp  = (const float*)d_in[4];
    const float* bp  = (const float*)d_in[5];
    float* out = (float*)d_out;

    const size_t smem = SMEM_FLOATS * sizeof(float);   // 225,280 bytes
    cudaFuncSetAttribute(local_attn_kernel,
                         cudaFuncAttributeMaxDynamicSharedMemorySize, (int)smem);
    local_attn_kernel<<<4096, NT, smem>>>(x, Wq, Wkv, pos, Wp, bp, out);
}

// round 6
// speedup vs baseline: 1.0008x; 1.0008x over previous
#include <cuda_runtime.h>

#define NT 512
typedef unsigned long long ull;

// ---------- packed f32x2 helpers (Blackwell sm_103a) ----------
__device__ __forceinline__ ull pk(float lo, float hi) {
    ull r; asm("mov.b64 %0,{%1,%2};" : "=l"(r) : "f"(lo), "f"(hi)); return r;
}
__device__ __forceinline__ float2 upk(ull v) {
    float2 f; asm("mov.b64 {%0,%1},%2;" : "=f"(f.x), "=f"(f.y) : "l"(v)); return f;
}
__device__ __forceinline__ ull fma2(ull a, ull b, ull c) {
    ull d; asm("fma.rn.f32x2 %0,%1,%2,%3;" : "=l"(d) : "l"(a), "l"(b), "l"(c)); return d;
}

// smem layout (floats)
#define OFF_XWT 0            // [256][68]  xwT[c][row]
#define OFF_QT  17408        // [64][68]   qT[d_local][i]   (2 heads)
#define OFF_KT  21760        // [64][68]
#define OFF_VB  26112        // [64][64]   vb[j][d_local]
#define OFF_P2  30208        // [2][64][68]
#define OFF_OBT 38912        // [256][68]  obT[c][i]
#define SMEM_FLOATS 56320    // 225,280 bytes

__global__ void __launch_bounds__(NT, 1)
local_attn_kernel(const float* __restrict__ x,
                  const float* __restrict__ Wq,
                  const float* __restrict__ Wkv,
                  const float* __restrict__ pos,
                  const float* __restrict__ Wp,
                  const float* __restrict__ bp,
                  float* __restrict__ out)
{
    extern __shared__ float sm[];
    float* xwT = sm + OFF_XWT;
    float* qT  = sm + OFF_QT;
    float* kT  = sm + OFF_KT;
    float* vb  = sm + OFF_VB;
    float* P2  = sm + OFF_P2;
    float* obT = sm + OFF_OBT;

    const int t   = threadIdx.x;
    const int wid = blockIdx.x;
    const int b  = wid >> 10;
    const int nh = (wid >> 5) & 31;
    const int nw = wid & 31;

    const float* xbase = x + (((b * 256 + nh * 8) * 256 + nw * 8) << 8);

    // ---------------- Phase A: load + transpose window into xwT[c][row] ----------------
    {
        const int c  = t & 255;
        const int r0 = t >> 8;           // 0,1
        #pragma unroll
        for (int rep = 0; rep < 32; ++rep) {
            int row = r0 + rep * 2;
            int i = row >> 3, j = row & 7;
            float v = __ldg(xbase + i * 65536 + j * 256 + c);
            xwT[c * 68 + row] = v;
        }
    }
    __syncthreads();

    // thread mappings
    const int rg = t >> 6;      // 0..7  (QKV / proj row group: rows rg*8..rg*8+7)
    const int cg = t & 63;      // 0..63 (QKV / proj col)
    const int sh   = t >> 8;        // 0/1 head-local (sim/av)
    const int sidx = t & 255;
    const int sig  = sidx >> 3;     // 0..31 (sim: rows sig*2, sig*2+1)
    const int sjg  = sidx & 7;      // 0..7  (sim: cols sjg*8..+7)
    const int aig  = sidx >> 2;     // 0..63 (av: row)
    const int adg  = sidx & 3;      // 0..3  (av: cols adg*8..+7)

    const float qscale = 0.17677669529663687f;

    for (int hb = 0; hb < 4; ++hb) {
        // ---------------- QKV: C[64 x 192] = xw @ [Wq|Wk|Wv] (2 heads) ----------------
        {
            ull aq[4], ak[4], avv[4];
            #pragma unroll
            for (int i = 0; i < 4; ++i) { aq[i] = 0ULL; ak[i] = 0ULL; avv[i] = 0ULL; }
            const float* wqp = Wq  + hb * 64 + cg;
            const float* wkp = Wkv + hb * 64 + cg;
            const float* wvp = Wkv + 256 + hb * 64 + cg;
            const float* xp  = xwT + rg * 8;
            #pragma unroll 4
            for (int c = 0; c < 256; ++c) {
                float wq = __ldg(wqp + c * 256);
                float wk = __ldg(wkp + c * 512);
                float wv = __ldg(wvp + c * 512);
                ull bq = pk(wq, wq), bk = pk(wk, wk), bv = pk(wv, wv);
                ulonglong2 xa = *(const ulonglong2*)(xp + c * 68);
                ulonglong2 xb = *(const ulonglong2*)(xp + c * 68 + 4);
                aq[0] = fma2(xa.x, bq, aq[0]);  ak[0] = fma2(xa.x, bk, ak[0]);  avv[0] = fma2(xa.x, bv, avv[0]);
                aq[1] = fma2(xa.y, bq, aq[1]);  ak[1] = fma2(xa.y, bk, ak[1]);  avv[1] = fma2(xa.y, bv, avv[1]);
                aq[2] = fma2(xb.x, bq, aq[2]);  ak[2] = fma2(xb.x, bk, ak[2]);  avv[2] = fma2(xb.x, bv, avv[2]);
                aq[3] = fma2(xb.y, bq, aq[3]);  ak[3] = fma2(xb.y, bk, ak[3]);  avv[3] = fma2(xb.y, bv, avv[3]);
            }
            #pragma unroll
            for (int p = 0; p < 4; ++p) {
                float2 fq = upk(aq[p]);
                float2 fk = upk(ak[p]);
                float2 fv = upk(avv[p]);
                int r = rg * 8 + p * 2;
                qT[cg * 68 + r]     = fq.x * qscale;
                qT[cg * 68 + r + 1] = fq.y * qscale;
                kT[cg * 68 + r]     = fk.x;
                kT[cg * 68 + r + 1] = fk.y;
                vb[r * 64 + cg]       = fv.x;
                vb[(r + 1) * 64 + cg] = fv.y;
            }
        }
        __syncthreads();

        // ---------------- sim = q k^T + pos ; softmax ----------------
        {
            const int hq = sh * 32;
            ull s0[4], s1[4];
            #pragma unroll
            for (int i = 0; i < 4; ++i) { s0[i] = 0ULL; s1[i] = 0ULL; }
            #pragma unroll 4
            for (int d = 0; d < 32; ++d) {
                float2 qv = *(const float2*)(qT + (hq + d) * 68 + sig * 2);
                ull q0 = pk(qv.x, qv.x);
                ull q1 = pk(qv.y, qv.y);
                const float* kr = kT + (hq + d) * 68 + sjg * 8;
                ulonglong2 ka = *(const ulonglong2*)(kr);
                ulonglong2 kb = *(const ulonglong2*)(kr + 4);
                s0[0] = fma2(q0, ka.x, s0[0]);  s1[0] = fma2(q1, ka.x, s1[0]);
                s0[1] = fma2(q0, ka.y, s0[1]);  s1[1] = fma2(q1, ka.y, s1[1]);
                s0[2] = fma2(q0, kb.x, s0[2]);  s1[2] = fma2(q1, kb.x, s1[2]);
                s0[3] = fma2(q0, kb.y, s0[3]);  s1[3] = fma2(q1, kb.y, s1[3]);
            }
            const int i0 = sig * 2;
            const int hcur = hb * 2 + sh;
            const float* pp = pos + hcur * 4096 + i0 * 64 + sjg * 8;
            float sv0[8], sv1[8];
            #pragma unroll
            for (int p = 0; p < 4; ++p) {
                float2 f0 = upk(s0[p]); sv0[p * 2] = f0.x; sv0[p * 2 + 1] = f0.y;
                float2 f1 = upk(s1[p]); sv1[p * 2] = f1.x; sv1[p * 2 + 1] = f1.y;
            }
            #pragma unroll
            for (int jj = 0; jj < 8; ++jj) {
                sv0[jj] += __ldg(pp + jj);
                sv1[jj] += __ldg(pp + 64 + jj);
            }
            float m0 = sv0[0], m1 = sv1[0];
            #pragma unroll
            for (int jj = 1; jj < 8; ++jj) { m0 = fmaxf(m0, sv0[jj]); m1 = fmaxf(m1, sv1[jj]); }
            #pragma unroll
            for (int o = 1; o < 8; o <<= 1) {
                m0 = fmaxf(m0, __shfl_xor_sync(0xffffffffu, m0, o));
                m1 = fmaxf(m1, __shfl_xor_sync(0xffffffffu, m1, o));
            }
            float su0 = 0.f, su1 = 0.f;
            #pragma unroll
            for (int jj = 0; jj < 8; ++jj) {
                sv0[jj] = __expf(sv0[jj] - m0); su0 += sv0[jj];
                sv1[jj] = __expf(sv1[jj] - m1); su1 += sv1[jj];
            }
            #pragma unroll
            for (int o = 1; o < 8; o <<= 1) {
                su0 += __shfl_xor_sync(0xffffffffu, su0, o);
                su1 += __shfl_xor_sync(0xffffffffu, su1, o);
            }
            float inv0 = 1.f / su0, inv1 = 1.f / su1;
            float* pr = P2 + sh * 4352 + i0 * 68 + sjg * 8;
            *(float4*)(pr)          = make_float4(sv0[0]*inv0, sv0[1]*inv0, sv0[2]*inv0, sv0[3]*inv0);
            *(float4*)(pr + 4)      = make_float4(sv0[4]*inv0, sv0[5]*inv0, sv0[6]*inv0, sv0[7]*inv0);
            *(float4*)(pr + 68)     = make_float4(sv1[0]*inv1, sv1[1]*inv1, sv1[2]*inv1, sv1[3]*inv1);
            *(float4*)(pr + 68 + 4) = make_float4(sv1[4]*inv1, sv1[5]*inv1, sv1[6]*inv1, sv1[7]*inv1);
        }
        __syncthreads();

        // ---------------- av: out_h = P @ V ----------------
        {
            ull o[4] = {0ULL, 0ULL, 0ULL, 0ULL};
            const float* pr = P2 + sh * 4352 + aig * 68;
            const float* vp = vb + sh * 32 + adg * 8;
            #pragma unroll 4
            for (int j = 0; j < 64; ++j) {
                float p = pr[j];
                ull pb = pk(p, p);
                ulonglong2 va = *(const ulonglong2*)(vp + j * 64);
                ulonglong2 vbq = *(const ulonglong2*)(vp + j * 64 + 4);
                o[0] = fma2(pb, va.x, o[0]);
                o[1] = fma2(pb, va.y, o[1]);
                o[2] = fma2(pb, vbq.x, o[2]);
                o[3] = fma2(pb, vbq.y, o[3]);
            }
            const int dbase = (hb * 2 + sh) * 32 + adg * 8;
            #pragma unroll
            for (int p = 0; p < 4; ++p) {
                float2 f = upk(o[p]);
                obT[(dbase + p * 2) * 68 + aig]     = f.x;
                obT[(dbase + p * 2 + 1) * 68 + aig] = f.y;
            }
        }
        __syncthreads();
    }

    // ---------------- Projection: out = obT^T @ Wp + bp ----------------
    {
        ull acc[4][4];   // [col][row-pair]
        #pragma unroll
        for (int a = 0; a < 4; ++a)
            #pragma unroll
            for (int p = 0; p < 4; ++p) acc[a][p] = 0ULL;
        const float* wpp = Wp + cg * 4;
        const float* op  = obT + rg * 8;
        #pragma unroll 2
        for (int c = 0; c < 256; ++c) {
            float4 w = __ldg((const float4*)(wpp + c * 256));
            ull w0 = pk(w.x, w.x), w1 = pk(w.y, w.y), w2 = pk(w.z, w.z), w3 = pk(w.w, w.w);
            ulonglong2 xa = *(const ulonglong2*)(op + c * 68);
            ulonglong2 xb = *(const ulonglong2*)(op + c * 68 + 4);
            acc[0][0] = fma2(xa.x, w0, acc[0][0]);  acc[1][0] = fma2(xa.x, w1, acc[1][0]);
            acc[2][0] = fma2(xa.x, w2, acc[2][0]);  acc[3][0] = fma2(xa.x, w3, acc[3][0]);
            acc[0][1] = fma2(xa.y, w0, acc[0][1]);  acc[1][1] = fma2(xa.y, w1, acc[1][1]);
            acc[2][1] = fma2(xa.y, w2, acc[2][1]);  acc[3][1] = fma2(xa.y, w3, acc[3][1]);
            acc[0][2] = fma2(xb.x, w0, acc[0][2]);  acc[1][2] = fma2(xb.x, w1, acc[1][2]);
            acc[2][2] = fma2(xb.x, w2, acc[2][2]);  acc[3][2] = fma2(xb.x, w3, acc[3][2]);
            acc[0][3] = fma2(xb.y, w0, acc[0][3]);  acc[1][3] = fma2(xb.y, w1, acc[1][3]);
            acc[2][3] = fma2(xb.y, w2, acc[2][3]);  acc[3][3] = fma2(xb.y, w3, acc[3][3]);
        }
        float4 bias = __ldg((const float4*)(bp + cg * 4));
        float* obase = out + (((b * 256 + nh * 8) * 256 + nw * 8) << 8) + cg * 4;
        #pragma unroll
        for (int p = 0; p < 4; ++p) {
            float2 c0 = upk(acc[0][p]);
            float2 c1 = upk(acc[1][p]);
            float2 c2 = upk(acc[2][p]);
            float2 c3 = upk(acc[3][p]);
            int r = rg * 8 + p * 2;
            int i = r >> 3, j = r & 7;
            *(float4*)(obase + i * 65536 + j * 256) =
                make_float4(c0.x + bias.x, c1.x + bias.y, c2.x + bias.z, c3.x + bias.w);
            r = r + 1; i = r >> 3; j = r & 7;
            *(float4*)(obase + i * 65536 + j * 256) =
                make_float4(c0.y + bias.x, c1.y + bias.y, c2.y + bias.z, c3.y + bias.w);
        }
    }
}

extern "C" void kernel_launch(void* const* d_in, const int* in_sizes, int n_in,
                              void* d_out, int out_size)
{
    const float* x   = (const float*)d_in[0];
    const float* Wq  = (const float*)d_in[1];
    const float* Wkv = (const float*)d_in[2];
    const float* pos = (const float*)d_in[3];
    const float* Wp  = (const float*)d_in[4];
    const float* bp  = (const float*)d_in[5];
    float* out = (float*)d_out;

    const size_t smem = SMEM_FLOATS * sizeof(float);   // 225,280 bytes
    cudaFuncSetAttribute(local_attn_kernel,
                         cudaFuncAttributeMaxDynamicSharedMemorySize, (int)smem);
    local_attn_kernel<<<4096, NT, smem>>>(x, Wq, Wkv, pos, Wp, bp, out);
}

// round 8
// speedup vs baseline: 1.8233x; 1.8219x over previous
#include <cuda_runtime.h>
#include <cuda_bf16.h>
#include <cstdint>

typedef unsigned long long ull;

#define QSCALE 0.17677669529663687f

// ---------------- global scratch ----------------
// Weight B-fragment images: [hi/lo][n-tile(128)][kt(16)][lane(32)][2 words]
__device__ uint32_t g_wB[2][128][16][32][2];
__device__ float g_qkv[4096ull * 64 * 768];   // [win][row][q(256,scaled)|k(256)|v(256)]
__device__ float g_ao [4096ull * 64 * 256];   // [win][row][c]

// ---------------- helpers ----------------
__device__ __forceinline__ uint32_t bfpack(float a, float b) {
    __nv_bfloat16 h0 = __float2bfloat16(a), h1 = __float2bfloat16(b);
    return (uint32_t)__bfloat16_as_ushort(h0) | ((uint32_t)__bfloat16_as_ushort(h1) << 16);
}
__device__ __forceinline__ ull pk(float lo, float hi){ ull r; asm("mov.b64 %0,{%1,%2};":"=l"(r):"f"(lo),"f"(hi)); return r; }
__device__ __forceinline__ float2 upk(ull v){ float2 f; asm("mov.b64 {%0,%1},%2;":"=f"(f.x),"=f"(f.y):"l"(v)); return f; }
__device__ __forceinline__ ull fma2(ull a, ull b, ull c){ ull d; asm("fma.rn.f32x2 %0,%1,%2,%3;":"=l"(d):"l"(a),"l"(b),"l"(c)); return d; }

__device__ __forceinline__ void mma_bf16(float* c, const uint32_t* a, const uint32_t* b) {
    asm volatile("mma.sync.aligned.m16n8k16.row.col.f32.bf16.bf16.f32 "
        "{%0,%1,%2,%3},{%4,%5,%6,%7},{%8,%9},{%0,%1,%2,%3};"
        : "+f"(c[0]), "+f"(c[1]), "+f"(c[2]), "+f"(c[3])
        : "r"(a[0]), "r"(a[1]), "r"(a[2]), "r"(a[3]), "r"(b[0]), "r"(b[1]));
}

// ---------------- k0: weights -> B-fragment hi/lo images ----------------
// global n ordering: [0,256)=Wq, [256,512)=Wkv.k, [512,768)=Wkv.v, [768,1024)=Wp
__global__ void k0_prep(const float* __restrict__ Wq, const float* __restrict__ Wkv,
                        const float* __restrict__ Wp) {
    int id = blockIdx.x * 512 + threadIdx.x;   // 131072
    int n = id >> 7, kp = id & 127;            // kp = k-word index (2 k's per word)
    int k = kp * 2;
    float w0, w1;
    if (n < 256)      { w0 = Wq [k*256 + n];            w1 = Wq [(k+1)*256 + n]; }
    else if (n < 512) { w0 = Wkv[k*512 + (n-256)];      w1 = Wkv[(k+1)*512 + (n-256)]; }
    else if (n < 768) { w0 = Wkv[k*512 + 256 + (n-512)];w1 = Wkv[(k+1)*512 + 256 + (n-512)]; }
    else              { w0 = Wp [k*256 + (n-768)];      w1 = Wp [(k+1)*256 + (n-768)]; }
    __nv_bfloat16 h0 = __float2bfloat16(w0), h1 = __float2bfloat16(w1);
    float l0f = w0 - __bfloat162float(h0), l1f = w1 - __bfloat162float(h1);
    int nt = n >> 3, kt = kp >> 3, kw = kp & 7;
    int lane = (n & 7) * 4 + (kw & 3), s = kw >> 2;
    g_wB[0][nt][kt][lane][s] = (uint32_t)__bfloat16_as_ushort(h0) |
                               ((uint32_t)__bfloat16_as_ushort(h1) << 16);
    g_wB[1][nt][kt][lane][s] = bfpack(l0f, l1f);
}

// ---------------- A staging: fp32 (r,4k) -> A-fragment hi/lo words ----------------
__device__ __forceinline__ void stageA(uint32_t* Ahi, uint32_t* Alo, int r, int k4, float4 v) {
    uint32_t hw[2], lw[2];
    {
        __nv_bfloat16 h0=__float2bfloat16(v.x), h1=__float2bfloat16(v.y);
        __nv_bfloat16 h2=__float2bfloat16(v.z), h3=__float2bfloat16(v.w);
        hw[0] = (uint32_t)__bfloat16_as_ushort(h0) | ((uint32_t)__bfloat16_as_ushort(h1) << 16);
        hw[1] = (uint32_t)__bfloat16_as_ushort(h2) | ((uint32_t)__bfloat16_as_ushort(h3) << 16);
        lw[0] = bfpack(v.x - __bfloat162float(h0), v.y - __bfloat162float(h1));
        lw[1] = bfpack(v.z - __bfloat162float(h2), v.w - __bfloat162float(h3));
    }
    int mt = r >> 4;
    #pragma unroll
    for (int w = 0; w < 2; ++w) {
        int kp = 2 * k4 + w;
        int kt = kp >> 3, kw = kp & 7;
        int lane = ((r & 7) << 2) | (kw & 3);
        int s = ((r >> 3) & 1) | ((kw >> 2) << 1);
        int idx = (((mt * 16 + kt) * 32 + lane) << 2) | s;
        Ahi[idx] = hw[w];
        Alo[idx] = lw[w];
    }
}

// ---------------- per-warp GEMM over one n128 chunk (3-pass bf16) ----------------
__device__ __forceinline__ void gemm_chunk(const uint32_t* __restrict__ sAhi,
                                           const uint32_t* __restrict__ sAlo,
                                           const uint32_t* __restrict__ sBhi,
                                           const uint32_t* __restrict__ sBlo,
                                           int mw, int nwp, int lane, float acc[4][4]) {
    #pragma unroll
    for (int nt = 0; nt < 4; ++nt)
        #pragma unroll
        for (int i = 0; i < 4; ++i) acc[nt][i] = 0.f;
    #pragma unroll
    for (int kt = 0; kt < 16; ++kt) {
        uint32_t ah[4], al[4];
        int aoff = ((mw * 16 + kt) * 32 + lane) << 2;
        *(uint4*)ah = *(const uint4*)(sAhi + aoff);
        *(uint4*)al = *(const uint4*)(sAlo + aoff);
        uint32_t bh[4][2], bl[4][2];
        #pragma unroll
        for (int nt = 0; nt < 4; ++nt) {
            int boff = (((nwp * 4 + nt) * 16 + kt) * 32 + lane) << 1;
            *(uint2*)bh[nt] = *(const uint2*)(sBhi + boff);
            *(uint2*)bl[nt] = *(const uint2*)(sBlo + boff);
        }
        #pragma unroll
        for (int nt = 0; nt < 4; ++nt) mma_bf16(acc[nt], ah, bh[nt]);
        #pragma unroll
        for (int nt = 0; nt < 4; ++nt) mma_bf16(acc[nt], al, bh[nt]);
        #pragma unroll
        for (int nt = 0; nt < 4; ++nt) mma_bf16(acc[nt], ah, bl[nt]);
    }
}

// smem word layout (uint32): Ahi[8192] Alo[8192] Bhi[16384] Blo[16384] = 196608 B
#define SMEM_G 196608

// ---------------- k1: QKV GEMM ----------------
__global__ void __launch_bounds__(512, 1)
k1_qkv(const float* __restrict__ x) {
    extern __shared__ uint32_t sm[];
    uint32_t* sAhi = sm;
    uint32_t* sAlo = sm + 8192;
    uint32_t* sBhi = sm + 16384;
    uint32_t* sBlo = sm + 32768;
    const int t = threadIdx.x, win = blockIdx.x;
    const int b = win >> 10, nh = (win >> 5) & 31, nww = win & 31;
    const float* xb = x + (((size_t)(b * 256 + nh * 8) * 256 + nww * 8) << 8);

    #pragma unroll
    for (int rep = 0; rep < 8; ++rep) {
        int task = t + rep * 512;
        int r = task >> 6, k4 = task & 63;
        float4 v = *(const float4*)(xb + (size_t)(r >> 3) * 65536 + (r & 7) * 256 + k4 * 4);
        stageA(sAhi, sAlo, r, k4, v);
    }

    const int w = t >> 5, lane = t & 31, mw = w >> 2, nwp = w & 3;
    float* dst = g_qkv + (size_t)win * 49152;

    for (int ch = 0; ch < 6; ++ch) {
        __syncthreads();
        const uint4* srcH = (const uint4*)&g_wB[0][ch * 16][0][0][0];
        const uint4* srcL = (const uint4*)&g_wB[1][ch * 16][0][0][0];
        uint4* dH = (uint4*)sBhi;
        uint4* dL = (uint4*)sBlo;
        #pragma unroll
        for (int i = 0; i < 8; ++i) {
            dH[t + i * 512] = srcH[t + i * 512];
            dL[t + i * 512] = srcL[t + i * 512];
        }
        __syncthreads();
        float acc[4][4];
        gemm_chunk(sAhi, sAlo, sBhi, sBlo, mw, nwp, lane, acc);
        float sc = (ch < 2) ? QSCALE : 1.0f;
        int row = mw * 16 + (lane >> 2);
        int col = ch * 128 + nwp * 32 + (lane & 3) * 2;
        #pragma unroll
        for (int nt = 0; nt < 4; ++nt) {
            float* p = dst + row * 768 + col + nt * 8;
            *(float2*)p             = make_float2(acc[nt][0] * sc, acc[nt][1] * sc);
            *(float2*)(p + 8 * 768) = make_float2(acc[nt][2] * sc, acc[nt][3] * sc);
        }
    }
}

// ---------------- k2: attention (fp32 SIMT, proven R2 math) ----------------
__global__ void __launch_bounds__(512, 2)
k2_attn(const float* __restrict__ pos) {
    extern __shared__ float sf[];
    float* qT = sf;               // [64 c][68]
    float* kT = sf + 4352;
    float* vbuf = sf + 8704;      // [64 j][64 c]
    float* P2 = sf + 12800;       // [2][64][68]
    const int t = threadIdx.x, win = blockIdx.x;
    const float* src = g_qkv + (size_t)win * 49152;
    float* aout = g_ao + (size_t)win * 16384;
    const int sh = t >> 8, sidx = t & 255;
    const int sig = sidx >> 3, sjg = sidx & 7, aig = sidx >> 2, adg = sidx & 3;

    for (int hb = 0; hb < 4; ++hb) {
        #pragma unroll
        for (int rep = 0; rep < 2; ++rep) {
            int task = t + rep * 512, row = task >> 4, c4 = task & 15;
            const float* s = src + row * 768 + hb * 64 + c4 * 4;
            float4 q4 = *(const float4*)(s);
            float4 k4 = *(const float4*)(s + 256);
            float4 v4 = *(const float4*)(s + 512);
            int c = c4 * 4;
            qT[c*68+row]=q4.x; qT[(c+1)*68+row]=q4.y; qT[(c+2)*68+row]=q4.z; qT[(c+3)*68+row]=q4.w;
            kT[c*68+row]=k4.x; kT[(c+1)*68+row]=k4.y; kT[(c+2)*68+row]=k4.z; kT[(c+3)*68+row]=k4.w;
            *(float4*)(vbuf + row * 64 + c) = v4;
        }
        __syncthreads();
        {   // sim + softmax
            const int hq = sh * 32;
            ull s0[4] = {0,0,0,0}, s1[4] = {0,0,0,0};
            #pragma unroll 4
            for (int d = 0; d < 32; ++d) {
                float2 qv = *(const float2*)(qT + (hq + d) * 68 + sig * 2);
                ull q0 = pk(qv.x, qv.x), q1 = pk(qv.y, qv.y);
                const float* kr = kT + (hq + d) * 68 + sjg * 8;
                ulonglong2 ka = *(const ulonglong2*)(kr);
                ulonglong2 kb = *(const ulonglong2*)(kr + 4);
                s0[0]=fma2(q0,ka.x,s0[0]); s1[0]=fma2(q1,ka.x,s1[0]);
                s0[1]=fma2(q0,ka.y,s0[1]); s1[1]=fma2(q1,ka.y,s1[1]);
                s0[2]=fma2(q0,kb.x,s0[2]); s1[2]=fma2(q1,kb.x,s1[2]);
                s0[3]=fma2(q0,kb.y,s0[3]); s1[3]=fma2(q1,kb.y,s1[3]);
            }
            const int i0 = sig * 2, hcur = hb * 2 + sh;
            const float* pp = pos + hcur * 4096 + i0 * 64 + sjg * 8;
            float sv0[8], sv1[8];
            #pragma unroll
            for (int p = 0; p < 4; ++p) {
                float2 f0 = upk(s0[p]); sv0[p*2]=f0.x; sv0[p*2+1]=f0.y;
                float2 f1 = upk(s1[p]); sv1[p*2]=f1.x; sv1[p*2+1]=f1.y;
            }
            #pragma unroll
            for (int jj = 0; jj < 8; ++jj) { sv0[jj] += __ldg(pp + jj); sv1[jj] += __ldg(pp + 64 + jj); }
            float m0 = sv0[0], m1 = sv1[0];
            #pragma unroll
            for (int jj = 1; jj < 8; ++jj) { m0 = fmaxf(m0, sv0[jj]); m1 = fmaxf(m1, sv1[jj]); }
            #pragma unroll
            for (int o = 1; o < 8; o <<= 1) {
                m0 = fmaxf(m0, __shfl_xor_sync(0xffffffffu, m0, o));
                m1 = fmaxf(m1, __shfl_xor_sync(0xffffffffu, m1, o));
            }
            float su0 = 0.f, su1 = 0.f;
            #pragma unroll
            for (int jj = 0; jj < 8; ++jj) {
                sv0[jj] = __expf(sv0[jj] - m0); su0 += sv0[jj];
                sv1[jj] = __expf(sv1[jj] - m1); su1 += sv1[jj];
            }
            #pragma unroll
            for (int o = 1; o < 8; o <<= 1) {
                su0 += __shfl_xor_sync(0xffffffffu, su0, o);
                su1 += __shfl_xor_sync(0xffffffffu, su1, o);
            }
            float inv0 = 1.f / su0, inv1 = 1.f / su1;
            float* pr = P2 + sh * 4352 + i0 * 68 + sjg * 8;
            *(float4*)(pr)      = make_float4(sv0[0]*inv0, sv0[1]*inv0, sv0[2]*inv0, sv0[3]*inv0);
            *(float4*)(pr+4)    = make_float4(sv0[4]*inv0, sv0[5]*inv0, sv0[6]*inv0, sv0[7]*inv0);
            *(float4*)(pr+68)   = make_float4(sv1[0]*inv1, sv1[1]*inv1, sv1[2]*inv1, sv1[3]*inv1);
            *(float4*)(pr+68+4) = make_float4(sv1[4]*inv1, sv1[5]*inv1, sv1[6]*inv1, sv1[7]*inv1);
        }
        __syncthreads();
        {   // av
            ull o[4] = {0,0,0,0};
            const float* pr = P2 + sh * 4352 + aig * 68;
            const float* vp = vbuf + sh * 32 + adg * 8;
            #pragma unroll 4
            for (int j = 0; j < 64; ++j) {
                float p = pr[j]; ull pb = pk(p, p);
                ulonglong2 va = *(const ulonglong2*)(vp + j * 64);
                ulonglong2 vb2 = *(const ulonglong2*)(vp + j * 64 + 4);
                o[0]=fma2(pb,va.x,o[0]); o[1]=fma2(pb,va.y,o[1]);
                o[2]=fma2(pb,vb2.x,o[2]); o[3]=fma2(pb,vb2.y,o[3]);
            }
            int dbase = (hb * 2 + sh) * 32 + adg * 8;
            float2 f0=upk(o[0]), f1=upk(o[1]), f2=upk(o[2]), f3=upk(o[3]);
            *(float4*)(aout + aig * 256 + dbase)     = make_float4(f0.x, f0.y, f1.x, f1.y);
            *(float4*)(aout + aig * 256 + dbase + 4) = make_float4(f2.x, f2.y, f3.x, f3.y);
        }
        __syncthreads();
    }
}

// ---------------- k3: projection GEMM + bias + un-window ----------------
__global__ void __launch_bounds__(512, 1)
k3_proj(const float* __restrict__ bp, float* __restrict__ out) {
    extern __shared__ uint32_t sm[];
    uint32_t* sAhi = sm;
    uint32_t* sAlo = sm + 8192;
    uint32_t* sBhi = sm + 16384;
    uint32_t* sBlo = sm + 32768;
    const int t = threadIdx.x, win = blockIdx.x;
    const float* ao = g_ao + (size_t)win * 16384;

    #pragma unroll
    for (int rep = 0; rep < 8; ++rep) {
        int task = t + rep * 512;
        int r = task >> 6, k4 = task & 63;
        float4 v = *(const float4*)(ao + r * 256 + k4 * 4);
        stageA(sAhi, sAlo, r, k4, v);
    }

    const int w = t >> 5, lane = t & 31, mw = w >> 2, nwp = w & 3;
    const int b = win >> 10, nh = (win >> 5) & 31, nww = win & 31;
    float* obase = out + (((size_t)(b * 256 + nh * 8) * 256 + nww * 8) << 8);

    for (int ch = 0; ch < 2; ++ch) {
        __syncthreads();
        const uint4* srcH = (const uint4*)&g_wB[0][96 + ch * 16][0][0][0];
        const uint4* srcL = (const uint4*)&g_wB[1][96 + ch * 16][0][0][0];
        uint4* dH = (uint4*)sBhi;
        uint4* dL = (uint4*)sBlo;
        #pragma unroll
        for (int i = 0; i < 8; ++i) {
            dH[t + i * 512] = srcH[t + i * 512];
            dL[t + i * 512] = srcL[t + i * 512];
        }
        __syncthreads();
        float acc[4][4];
        gemm_chunk(sAhi, sAlo, sBhi, sBlo, mw, nwp, lane, acc);
        int row = mw * 16 + (lane >> 2);
        int col = ch * 128 + nwp * 32 + (lane & 3) * 2;
        #pragma unroll
        for (int nt = 0; nt < 4; ++nt) {
            int c = col + nt * 8;
            float2 bias = *(const float2*)(bp + c);
            int r0 = row, r1 = row + 8;
            *(float2*)(obase + (r0 >> 3) * 65536 + (r0 & 7) * 256 + c) =
                make_float2(acc[nt][0] + bias.x, acc[nt][1] + bias.y);
            *(float2*)(obase + (r1 >> 3) * 65536 + (r1 & 7) * 256 + c) =
                make_float2(acc[nt][2] + bias.x, acc[nt][3] + bias.y);
        }
    }
}

extern "C" void kernel_launch(void* const* d_in, const int* in_sizes, int n_in,
                              void* d_out, int out_size)
{
    const float* x   = (const float*)d_in[0];
    const float* Wq  = (const float*)d_in[1];
    const float* Wkv = (const float*)d_in[2];
    const float* pos = (const float*)d_in[3];
    const float* Wp  = (const float*)d_in[4];
    const float* bp  = (const float*)d_in[5];
    float* out = (float*)d_out;

    cudaFuncSetAttribute(k1_qkv,  cudaFuncAttributeMaxDynamicSharedMemorySize, SMEM_G);
    cudaFuncSetAttribute(k3_proj, cudaFuncAttributeMaxDynamicSharedMemorySize, SMEM_G);
    cudaFuncSetAttribute(k2_attn, cudaFuncAttributeMaxDynamicSharedMemorySize, 86016);

    k0_prep<<<256, 512>>>(Wq, Wkv, Wp);
    k1_qkv<<<4096, 512, SMEM_G>>>(x);
    k2_attn<<<4096, 512, 86016>>>(pos);
    k3_proj<<<4096, 512, SMEM_G>>>(bp, out);
}

// round 10
// speedup vs baseline: 2.0314x; 1.1141x over previous
#include <cuda_runtime.h>
#include <cuda_bf16.h>
#include <cuda_fp16.h>
#include <cstdint>

typedef unsigned long long ull;

#define QSCALE 0.17677669529663687f

// ---------------- global scratch ----------------
__device__ uint32_t g_wB[2][128][16][32][2];  // bf16 hi/lo B-frag images (Wq|Wk|Wv|Wp)
__device__ uint32_t g_wP[32][16][32][2];      // fp16 B-frag image (Wp)
__device__ float g_qkv[4096ull * 64 * 768];   // [win][row][q(256,scaled)|k(256)|v(256)]
__device__ float g_ao [4096ull * 64 * 256];   // [win][row][c]

// ---------------- helpers ----------------
__device__ __forceinline__ uint32_t bfpack(float a, float b) {
    __nv_bfloat16 h0 = __float2bfloat16(a), h1 = __float2bfloat16(b);
    return (uint32_t)__bfloat16_as_ushort(h0) | ((uint32_t)__bfloat16_as_ushort(h1) << 16);
}
__device__ __forceinline__ uint32_t hpack(float a, float b) {
    __half2 h = __floats2half2_rn(a, b);
    return *(uint32_t*)&h;
}
__device__ __forceinline__ ull pk(float lo, float hi){ ull r; asm("mov.b64 %0,{%1,%2};":"=l"(r):"f"(lo),"f"(hi)); return r; }
__device__ __forceinline__ float2 upk(ull v){ float2 f; asm("mov.b64 {%0,%1},%2;":"=f"(f.x),"=f"(f.y):"l"(v)); return f; }
__device__ __forceinline__ ull fma2(ull a, ull b, ull c){ ull d; asm("fma.rn.f32x2 %0,%1,%2,%3;":"=l"(d):"l"(a),"l"(b),"l"(c)); return d; }

__device__ __forceinline__ void mma_bf16(float* c, const uint32_t* a, const uint32_t* b) {
    asm volatile("mma.sync.aligned.m16n8k16.row.col.f32.bf16.bf16.f32 "
        "{%0,%1,%2,%3},{%4,%5,%6,%7},{%8,%9},{%0,%1,%2,%3};"
        : "+f"(c[0]), "+f"(c[1]), "+f"(c[2]), "+f"(c[3])
        : "r"(a[0]), "r"(a[1]), "r"(a[2]), "r"(a[3]), "r"(b[0]), "r"(b[1]));
}
__device__ __forceinline__ void mma_f16(float* c, const uint32_t* a, const uint32_t* b) {
    asm volatile("mma.sync.aligned.m16n8k16.row.col.f32.f16.f16.f32 "
        "{%0,%1,%2,%3},{%4,%5,%6,%7},{%8,%9},{%0,%1,%2,%3};"
        : "+f"(c[0]), "+f"(c[1]), "+f"(c[2]), "+f"(c[3])
        : "r"(a[0]), "r"(a[1]), "r"(a[2]), "r"(a[3]), "r"(b[0]), "r"(b[1]));
}

// ---------------- k0: weights -> fragment images ----------------
// n ordering: [0,256)=Wq, [256,512)=Wkv.k, [512,768)=Wkv.v, [768,1024)=Wp
__global__ void k0_prep(const float* __restrict__ Wq, const float* __restrict__ Wkv,
                        const float* __restrict__ Wp) {
    int id = blockIdx.x * 512 + threadIdx.x;   // 131072
    int n = id >> 7, kp = id & 127;
    int k = kp * 2;
    float w0, w1;
    if (n < 256)      { w0 = Wq [k*256 + n];            w1 = Wq [(k+1)*256 + n]; }
    else if (n < 512) { w0 = Wkv[k*512 + (n-256)];      w1 = Wkv[(k+1)*512 + (n-256)]; }
    else if (n < 768) { w0 = Wkv[k*512 + 256 + (n-512)];w1 = Wkv[(k+1)*512 + 256 + (n-512)]; }
    else              { w0 = Wp [k*256 + (n-768)];      w1 = Wp [(k+1)*256 + (n-768)]; }
    __nv_bfloat16 h0 = __float2bfloat16(w0), h1 = __float2bfloat16(w1);
    float l0f = w0 - __bfloat162float(h0), l1f = w1 - __bfloat162float(h1);
    int nt = n >> 3, kt = kp >> 3, kw = kp & 7;
    int lane = (n & 7) * 4 + (kw & 3), s = kw >> 2;
    g_wB[0][nt][kt][lane][s] = (uint32_t)__bfloat16_as_ushort(h0) |
                               ((uint32_t)__bfloat16_as_ushort(h1) << 16);
    g_wB[1][nt][kt][lane][s] = bfpack(l0f, l1f);
    if (n >= 768) g_wP[nt - 96][kt][lane][s] = hpack(w0, w1);
}

// ---------------- A staging (bf16 hi/lo, kt-XOR swizzled) ----------------
__device__ __forceinline__ void stageA3(uint32_t* Ahi, uint32_t* Alo, int r, int k4, float4 v) {
    uint32_t hw[2], lw[2];
    {
        __nv_bfloat16 h0=__float2bfloat16(v.x), h1=__float2bfloat16(v.y);
        __nv_bfloat16 h2=__float2bfloat16(v.z), h3=__float2bfloat16(v.w);
        hw[0] = (uint32_t)__bfloat16_as_ushort(h0) | ((uint32_t)__bfloat16_as_ushort(h1) << 16);
        hw[1] = (uint32_t)__bfloat16_as_ushort(h2) | ((uint32_t)__bfloat16_as_ushort(h3) << 16);
        lw[0] = bfpack(v.x - __bfloat162float(h0), v.y - __bfloat162float(h1));
        lw[1] = bfpack(v.z - __bfloat162float(h2), v.w - __bfloat162float(h3));
    }
    int mt = r >> 4;
    #pragma unroll
    for (int w = 0; w < 2; ++w) {
        int kp = 2 * k4 + w;
        int kt = kp >> 3, kw = kp & 7;
        int lane = (((r & 7) << 2) | (kw & 3)) ^ (kt & 7);
        int s = ((r >> 3) & 1) | ((kw >> 2) << 1);
        int idx = (((mt * 16 + kt) * 32 + lane) << 2) | s;
        Ahi[idx] = hw[w];
        Alo[idx] = lw[w];
    }
}
// ---------------- A staging (fp16 single, kt-XOR swizzled) ----------------
__device__ __forceinline__ void stageA1h(uint32_t* A, int r, int k4, float4 v) {
    uint32_t hw[2] = { hpack(v.x, v.y), hpack(v.z, v.w) };
    int mt = r >> 4;
    #pragma unroll
    for (int w = 0; w < 2; ++w) {
        int kp = 2 * k4 + w;
        int kt = kp >> 3, kw = kp & 7;
        int lane = (((r & 7) << 2) | (kw & 3)) ^ (kt & 7);
        int s = ((r >> 3) & 1) | ((kw >> 2) << 1);
        A[(((mt * 16 + kt) * 32 + lane) << 2) | s] = hw[w];
    }
}

// ---------------- warp GEMM, 3-pass bf16, m32 x n32 tile ----------------
__device__ __forceinline__ void gemm3(const uint32_t* __restrict__ sAhi,
                                      const uint32_t* __restrict__ sAlo,
                                      const uint32_t* __restrict__ sBhi,
                                      const uint32_t* __restrict__ sBlo,
                                      int mw, int nwp, int lane, float acc[2][4][4]) {
    #pragma unroll
    for (int m = 0; m < 2; ++m)
        #pragma unroll
        for (int nt = 0; nt < 4; ++nt)
            #pragma unroll
            for (int i = 0; i < 4; ++i) acc[m][nt][i] = 0.f;
    #pragma unroll
    for (int kt = 0; kt < 16; ++kt) {
        int lx = lane ^ (kt & 7);
        uint32_t ah[2][4], al[2][4];
        #pragma unroll
        for (int m = 0; m < 2; ++m) {
            int aoff = (((2 * mw + m) * 16 + kt) * 32 + lx) << 2;
            *(uint4*)ah[m] = *(const uint4*)(sAhi + aoff);
            *(uint4*)al[m] = *(const uint4*)(sAlo + aoff);
        }
        uint32_t bh[4][2], bl[4][2];
        #pragma unroll
        for (int nt = 0; nt < 4; ++nt) {
            int boff = (((nwp * 4 + nt) * 16 + kt) * 32 + lane) << 1;
            *(uint2*)bh[nt] = *(const uint2*)(sBhi + boff);
            *(uint2*)bl[nt] = *(const uint2*)(sBlo + boff);
        }
        #pragma unroll
        for (int m = 0; m < 2; ++m)
            #pragma unroll
            for (int nt = 0; nt < 4; ++nt) mma_bf16(acc[m][nt], ah[m], bh[nt]);
        #pragma unroll
        for (int m = 0; m < 2; ++m)
            #pragma unroll
            for (int nt = 0; nt < 4; ++nt) mma_bf16(acc[m][nt], al[m], bh[nt]);
        #pragma unroll
        for (int m = 0; m < 2; ++m)
            #pragma unroll
            for (int nt = 0; nt < 4; ++nt) mma_bf16(acc[m][nt], ah[m], bl[nt]);
    }
}

// ---------------- warp GEMM, 1-pass fp16, m32 x n32 tile ----------------
__device__ __forceinline__ void gemm1h(const uint32_t* __restrict__ sA,
                                       const uint32_t* __restrict__ sB,
                                       int mw, int nwp, int lane, float acc[2][4][4]) {
    #pragma unroll
    for (int m = 0; m < 2; ++m)
        #pragma unroll
        for (int nt = 0; nt < 4; ++nt)
            #pragma unroll
            for (int i = 0; i < 4; ++i) acc[m][nt][i] = 0.f;
    #pragma unroll
    for (int kt = 0; kt < 16; ++kt) {
        int lx = lane ^ (kt & 7);
        uint32_t a[2][4];
        #pragma unroll
        for (int m = 0; m < 2; ++m)
            *(uint4*)a[m] = *(const uint4*)(sA + ((((2 * mw + m) * 16 + kt) * 32 + lx) << 2));
        uint32_t b[4][2];
        #pragma unroll
        for (int nt = 0; nt < 4; ++nt)
            *(uint2*)b[nt] = *(const uint2*)(sB + ((((nwp * 4 + nt) * 16 + kt) * 32 + lane) << 1));
        #pragma unroll
        for (int m = 0; m < 2; ++m)
            #pragma unroll
            for (int nt = 0; nt < 4; ++nt) mma_f16(acc[m][nt], a[m], b[nt]);
    }
}

// ---------------- k1: QKV GEMM (bf16 3-pass, M=64, 8 warps m32n32) ----------------
#define SMEM_K1 196608
__global__ void __launch_bounds__(256, 1)
k1_qkv(const float* __restrict__ x) {
    extern __shared__ uint32_t sm[];
    uint32_t* sAhi = sm;
    uint32_t* sAlo = sm + 8192;
    uint32_t* sBhi = sm + 16384;
    uint32_t* sBlo = sm + 32768;
    const int t = threadIdx.x, win = blockIdx.x;
    const int b = win >> 10, nh = (win >> 5) & 31, nww = win & 31;
    const float* xb = x + (((size_t)(b * 256 + nh * 8) * 256 + nww * 8) << 8);

    #pragma unroll
    for (int rep = 0; rep < 16; ++rep) {
        int task = t + rep * 256;
        int r = task >> 6, k4 = task & 63;
        float4 v = *(const float4*)(xb + (size_t)(r >> 3) * 65536 + (r & 7) * 256 + k4 * 4);
        stageA3(sAhi, sAlo, r, k4, v);
    }

    const int w = t >> 5, lane = t & 31, mw = w >> 2, nwp = w & 3;
    float* dst = g_qkv + (size_t)win * 49152;

    for (int ch = 0; ch < 6; ++ch) {
        __syncthreads();
        const uint4* srcH = (const uint4*)&g_wB[0][ch * 16][0][0][0];
        const uint4* srcL = (const uint4*)&g_wB[1][ch * 16][0][0][0];
        uint4* dH = (uint4*)sBhi;
        uint4* dL = (uint4*)sBlo;
        #pragma unroll
        for (int i = 0; i < 16; ++i) {
            dH[t + i * 256] = srcH[t + i * 256];
            dL[t + i * 256] = srcL[t + i * 256];
        }
        __syncthreads();
        float acc[2][4][4];
        gemm3(sAhi, sAlo, sBhi, sBlo, mw, nwp, lane, acc);
        float sc = (ch < 2) ? QSCALE : 1.0f;
        #pragma unroll
        for (int m = 0; m < 2; ++m) {
            int row = (2 * mw + m) * 16 + (lane >> 2);
            #pragma unroll
            for (int nt = 0; nt < 4; ++nt) {
                int col = ch * 128 + (nwp * 4 + nt) * 8 + (lane & 3) * 2;
                float* p = dst + row * 768 + col;
                *(float2*)p             = make_float2(acc[m][nt][0] * sc, acc[m][nt][1] * sc);
                *(float2*)(p + 8 * 768) = make_float2(acc[m][nt][2] * sc, acc[m][nt][3] * sc);
            }
        }
    }
}

// ---------------- k2: attention (fp32 SIMT, R8-proven, stride 68) ----------------
__global__ void __launch_bounds__(512, 2)
k2_attn(const float* __restrict__ pos) {
    extern __shared__ float sf[];
    float* qT = sf;               // [64 c][68]
    float* kT = sf + 4352;
    float* vbuf = sf + 8704;      // [64 j][64 c]
    float* P2 = sf + 12800;       // [2][64][68]
    const int t = threadIdx.x, win = blockIdx.x;
    const float* src = g_qkv + (size_t)win * 49152;
    float* aout = g_ao + (size_t)win * 16384;
    const int sh = t >> 8, sidx = t & 255;
    const int sig = sidx >> 3, sjg = sidx & 7, aig = sidx >> 2, adg = sidx & 3;

    for (int hb = 0; hb < 4; ++hb) {
        #pragma unroll
        for (int rep = 0; rep < 2; ++rep) {
            int task = t + rep * 512, row = task >> 4, c4 = task & 15;
            const float* s = src + row * 768 + hb * 64 + c4 * 4;
            float4 q4 = *(const float4*)(s);
            float4 k4 = *(const float4*)(s + 256);
            float4 v4 = *(const float4*)(s + 512);
            int c = c4 * 4;
            qT[c*68+row]=q4.x; qT[(c+1)*68+row]=q4.y; qT[(c+2)*68+row]=q4.z; qT[(c+3)*68+row]=q4.w;
            kT[c*68+row]=k4.x; kT[(c+1)*68+row]=k4.y; kT[(c+2)*68+row]=k4.z; kT[(c+3)*68+row]=k4.w;
            *(float4*)(vbuf + row * 64 + c) = v4;
        }
        __syncthreads();
        {   // sim + softmax
            const int hq = sh * 32;
            ull s0[4] = {0,0,0,0}, s1[4] = {0,0,0,0};
            #pragma unroll 4
            for (int d = 0; d < 32; ++d) {
                float2 qv = *(const float2*)(qT + (hq + d) * 68 + sig * 2);
                ull q0 = pk(qv.x, qv.x), q1 = pk(qv.y, qv.y);
                const float* kr = kT + (hq + d) * 68 + sjg * 8;
                ulonglong2 ka = *(const ulonglong2*)(kr);
                ulonglong2 kb = *(const ulonglong2*)(kr + 4);
                s0[0]=fma2(q0,ka.x,s0[0]); s1[0]=fma2(q1,ka.x,s1[0]);
                s0[1]=fma2(q0,ka.y,s0[1]); s1[1]=fma2(q1,ka.y,s1[1]);
                s0[2]=fma2(q0,kb.x,s0[2]); s1[2]=fma2(q1,kb.x,s1[2]);
                s0[3]=fma2(q0,kb.y,s0[3]); s1[3]=fma2(q1,kb.y,s1[3]);
            }
            const int i0 = sig * 2, hcur = hb * 2 + sh;
            const float* pp = pos + hcur * 4096 + i0 * 64 + sjg * 8;
            float sv0[8], sv1[8];
            #pragma unroll
            for (int p = 0; p < 4; ++p) {
                float2 f0 = upk(s0[p]); sv0[p*2]=f0.x; sv0[p*2+1]=f0.y;
                float2 f1 = upk(s1[p]); sv1[p*2]=f1.x; sv1[p*2+1]=f1.y;
            }
            #pragma unroll
            for (int jj = 0; jj < 8; ++jj) { sv0[jj] += __ldg(pp + jj); sv1[jj] += __ldg(pp + 64 + jj); }
            float m0 = sv0[0], m1 = sv1[0];
            #pragma unroll
            for (int jj = 1; jj < 8; ++jj) { m0 = fmaxf(m0, sv0[jj]); m1 = fmaxf(m1, sv1[jj]); }
            #pragma unroll
            for (int o = 1; o < 8; o <<= 1) {
                m0 = fmaxf(m0, __shfl_xor_sync(0xffffffffu, m0, o));
                m1 = fmaxf(m1, __shfl_xor_sync(0xffffffffu, m1, o));
            }
            float su0 = 0.f, su1 = 0.f;
            #pragma unroll
            for (int jj = 0; jj < 8; ++jj) {
                sv0[jj] = __expf(sv0[jj] - m0); su0 += sv0[jj];
                sv1[jj] = __expf(sv1[jj] - m1); su1 += sv1[jj];
            }
            #pragma unroll
            for (int o = 1; o < 8; o <<= 1) {
                su0 += __shfl_xor_sync(0xffffffffu, su0, o);
                su1 += __shfl_xor_sync(0xffffffffu, su1, o);
            }
            float inv0 = 1.f / su0, inv1 = 1.f / su1;
            float* pr = P2 + sh * 4352 + i0 * 68 + sjg * 8;
            *(float4*)(pr)      = make_float4(sv0[0]*inv0, sv0[1]*inv0, sv0[2]*inv0, sv0[3]*inv0);
            *(float4*)(pr+4)    = make_float4(sv0[4]*inv0, sv0[5]*inv0, sv0[6]*inv0, sv0[7]*inv0);
            *(float4*)(pr+68)   = make_float4(sv1[0]*inv1, sv1[1]*inv1, sv1[2]*inv1, sv1[3]*inv1);
            *(float4*)(pr+68+4) = make_float4(sv1[4]*inv1, sv1[5]*inv1, sv1[6]*inv1, sv1[7]*inv1);
        }
        __syncthreads();
        {   // av
            ull o[4] = {0,0,0,0};
            const float* pr = P2 + sh * 4352 + aig * 68;
            const float* vp = vbuf + sh * 32 + adg * 8;
            #pragma unroll 4
            for (int j = 0; j < 64; ++j) {
                float p = pr[j]; ull pb = pk(p, p);
                ulonglong2 va = *(const ulonglong2*)(vp + j * 64);
                ulonglong2 vb2 = *(const ulonglong2*)(vp + j * 64 + 4);
                o[0]=fma2(pb,va.x,o[0]); o[1]=fma2(pb,va.y,o[1]);
                o[2]=fma2(pb,vb2.x,o[2]); o[3]=fma2(pb,vb2.y,o[3]);
            }
            int dbase = (hb * 2 + sh) * 32 + adg * 8;
            float2 f0=upk(o[0]), f1=upk(o[1]), f2=upk(o[2]), f3=upk(o[3]);
            *(float4*)(aout + aig * 256 + dbase)     = make_float4(f0.x, f0.y, f1.x, f1.y);
            *(float4*)(aout + aig * 256 + dbase + 4) = make_float4(f2.x, f2.y, f3.x, f3.y);
        }
        __syncthreads();
    }
}

// ---------------- k3: projection (fp16 1-pass, M=64, 8 warps m32n32, occ 2) ----------------
#define SMEM_K3 98304
__global__ void __launch_bounds__(256, 2)
k3_proj(const float* __restrict__ bp, float* __restrict__ out) {
    extern __shared__ uint32_t sm[];
    uint32_t* sA = sm;
    uint32_t* sB = sm + 8192;
    const int t = threadIdx.x, win = blockIdx.x;
    const float* ao = g_ao + (size_t)win * 16384;

    #pragma unroll
    for (int rep = 0; rep < 16; ++rep) {
        int task = t + rep * 256;
        int r = task >> 6, k4 = task & 63;
        float4 v = *(const float4*)(ao + r * 256 + k4 * 4);
        stageA1h(sA, r, k4, v);
    }

    const int w = t >> 5, lane = t & 31, mw = w >> 2, nwp = w & 3;
    const int b = win >> 10, nh = (win >> 5) & 31, nww = win & 31;
    float* obase = out + (((size_t)(b * 256 + nh * 8) * 256 + nww * 8) << 8);

    for (int ch = 0; ch < 2; ++ch) {
        __syncthreads();
        const uint4* srcB = (const uint4*)&g_wP[ch * 16][0][0][0];
        uint4* dB = (uint4*)sB;
        #pragma unroll
        for (int i = 0; i < 16; ++i) dB[t + i * 256] = srcB[t + i * 256];
        __syncthreads();
        float acc[2][4][4];
        gemm1h(sA, sB, mw, nwp, lane, acc);
        #pragma unroll
        for (int m = 0; m < 2; ++m) {
            int row = (2 * mw + m) * 16 + (lane >> 2);
            #pragma unroll
            for (int nt = 0; nt < 4; ++nt) {
                int c = ch * 128 + (nwp * 4 + nt) * 8 + (lane & 3) * 2;
                float2 bias = *(const float2*)(bp + c);
                int r0 = row, r1 = row + 8;
                *(float2*)(obase + (r0 >> 3) * 65536 + (r0 & 7) * 256 + c) =
                    make_float2(acc[m][nt][0] + bias.x, acc[m][nt][1] + bias.y);
                *(float2*)(obase + (r1 >> 3) * 65536 + (r1 & 7) * 256 + c) =
                    make_float2(acc[m][nt][2] + bias.x, acc[m][nt][3] + bias.y);
            }
        }
    }
}

extern "C" void kernel_launch(void* const* d_in, const int* in_sizes, int n_in,
                              void* d_out, int out_size)
{
    const float* x   = (const float*)d_in[0];
    const float* Wq  = (const float*)d_in[1];
    const float* Wkv = (const float*)d_in[2];
    const float* pos = (const float*)d_in[3];
    const float* Wp  = (const float*)d_in[4];
    const float* bp  = (const float*)d_in[5];
    float* out = (float*)d_out;

    cudaFuncSetAttribute(k1_qkv,  cudaFuncAttributeMaxDynamicSharedMemorySize, SMEM_K1);
    cudaFuncSetAttribute(k2_attn, cudaFuncAttributeMaxDynamicSharedMemorySize, 86016);
    cudaFuncSetAttribute(k3_proj, cudaFuncAttributeMaxDynamicSharedMemorySize, SMEM_K3);

    k0_prep<<<256, 512>>>(Wq, Wkv, Wp);
    k1_qkv<<<4096, 256, SMEM_K1>>>(x);
    k2_attn<<<4096, 512, 86016>>>(pos);
    k3_proj<<<4096, 256, SMEM_K3>>>(bp, out);
}

// round 11
// speedup vs baseline: 2.6346x; 1.2970x over previous
#include <cuda_runtime.h>
#include <cuda_fp16.h>
#include <cstdint>

typedef unsigned long long ull;

#define QSCALE 0.17677669529663687f

// ---------------- global scratch ----------------
// fp16 B-fragment images, n ordering: [0,256)=Wq, [256,512)=Wkv.k, [512,768)=Wkv.v, [768,1024)=Wp
__device__ uint32_t g_wH[128][16][32][2];
__device__ __half g_qkv[4096ull * 64 * 768];  // [win][row][q(256,scaled)|k(256)|v(256)]
__device__ float  g_ao [4096ull * 64 * 256];  // [win][row][c]

// ---------------- helpers ----------------
__device__ __forceinline__ uint32_t hpack(float a, float b) {
    __half2 h = __floats2half2_rn(a, b);
    return *(uint32_t*)&h;
}
__device__ __forceinline__ ull pk(float lo, float hi){ ull r; asm("mov.b64 %0,{%1,%2};":"=l"(r):"f"(lo),"f"(hi)); return r; }
__device__ __forceinline__ float2 upk(ull v){ float2 f; asm("mov.b64 {%0,%1},%2;":"=f"(f.x),"=f"(f.y):"l"(v)); return f; }
__device__ __forceinline__ ull fma2(ull a, ull b, ull c){ ull d; asm("fma.rn.f32x2 %0,%1,%2,%3;":"=l"(d):"l"(a),"l"(b),"l"(c)); return d; }

__device__ __forceinline__ void mma_f16(float* c, const uint32_t* a, const uint32_t* b) {
    asm volatile("mma.sync.aligned.m16n8k16.row.col.f32.f16.f16.f32 "
        "{%0,%1,%2,%3},{%4,%5,%6,%7},{%8,%9},{%0,%1,%2,%3};"
        : "+f"(c[0]), "+f"(c[1]), "+f"(c[2]), "+f"(c[3])
        : "r"(a[0]), "r"(a[1]), "r"(a[2]), "r"(a[3]), "r"(b[0]), "r"(b[1]));
}

// ---------------- k0: weights -> fp16 B-fragment images ----------------
__global__ void k0_prep(const float* __restrict__ Wq, const float* __restrict__ Wkv,
                        const float* __restrict__ Wp) {
    int id = blockIdx.x * 512 + threadIdx.x;   // 131072
    int n = id >> 7, kp = id & 127;
    int k = kp * 2;
    float w0, w1;
    if (n < 256)      { w0 = Wq [k*256 + n];            w1 = Wq [(k+1)*256 + n]; }
    else if (n < 512) { w0 = Wkv[k*512 + (n-256)];      w1 = Wkv[(k+1)*512 + (n-256)]; }
    else if (n < 768) { w0 = Wkv[k*512 + 256 + (n-512)];w1 = Wkv[(k+1)*512 + 256 + (n-512)]; }
    else              { w0 = Wp [k*256 + (n-768)];      w1 = Wp [(k+1)*256 + (n-768)]; }
    int nt = n >> 3, kt = kp >> 3, kw = kp & 7;
    int lane = (n & 7) * 4 + (kw & 3), s = kw >> 2;
    g_wH[nt][kt][lane][s] = hpack(w0, w1);
}

// ---------------- A staging (fp16 single, kt-XOR swizzled) ----------------
__device__ __forceinline__ void stageA1h(uint32_t* A, int r, int k4, float4 v) {
    uint32_t hw[2] = { hpack(v.x, v.y), hpack(v.z, v.w) };
    int mt = r >> 4;
    #pragma unroll
    for (int w = 0; w < 2; ++w) {
        int kp = 2 * k4 + w;
        int kt = kp >> 3, kw = kp & 7;
        int lane = (((r & 7) << 2) | (kw & 3)) ^ (kt & 7);
        int s = ((r >> 3) & 1) | ((kw >> 2) << 1);
        A[(((mt * 16 + kt) * 32 + lane) << 2) | s] = hw[w];
    }
}

// ---------------- warp GEMM, 1-pass fp16, m32 x n32 tile ----------------
__device__ __forceinline__ void gemm1h(const uint32_t* __restrict__ sA,
                                       const uint32_t* __restrict__ sB,
                                       int mw, int nwp, int lane, float acc[2][4][4]) {
    #pragma unroll
    for (int m = 0; m < 2; ++m)
        #pragma unroll
        for (int nt = 0; nt < 4; ++nt)
            #pragma unroll
            for (int i = 0; i < 4; ++i) acc[m][nt][i] = 0.f;
    #pragma unroll
    for (int kt = 0; kt < 16; ++kt) {
        int lx = lane ^ (kt & 7);
        uint32_t a[2][4];
        #pragma unroll
        for (int m = 0; m < 2; ++m)
            *(uint4*)a[m] = *(const uint4*)(sA + ((((2 * mw + m) * 16 + kt) * 32 + lx) << 2));
        uint32_t b[4][2];
        #pragma unroll
        for (int nt = 0; nt < 4; ++nt)
            *(uint2*)b[nt] = *(const uint2*)(sB + ((((nwp * 4 + nt) * 16 + kt) * 32 + lane) << 1));
        #pragma unroll
        for (int m = 0; m < 2; ++m)
            #pragma unroll
            for (int nt = 0; nt < 4; ++nt) mma_f16(acc[m][nt], a[m], b[nt]);
    }
}

// ---------------- k1: QKV GEMM (fp16 1-pass, M=64, 8 warps m32n32, occ 2) ----------------
// smem words: sA[8192] sB[16384] = 96KB
#define SMEM_K1 98304
__global__ void __launch_bounds__(256, 2)
k1_qkv(const float* __restrict__ x) {
    extern __shared__ uint32_t sm[];
    uint32_t* sA = sm;
    uint32_t* sB = sm + 8192;
    const int t = threadIdx.x, win = blockIdx.x;
    const int b = win >> 10, nh = (win >> 5) & 31, nww = win & 31;
    const float* xb = x + (((size_t)(b * 256 + nh * 8) * 256 + nww * 8) << 8);

    #pragma unroll
    for (int rep = 0; rep < 16; ++rep) {
        int task = t + rep * 256;
        int r = task >> 6, k4 = task & 63;
        float4 v = *(const float4*)(xb + (size_t)(r >> 3) * 65536 + (r & 7) * 256 + k4 * 4);
        stageA1h(sA, r, k4, v);
    }

    const int w = t >> 5, lane = t & 31, mw = w >> 2, nwp = w & 3;
    __half* dst = g_qkv + (size_t)win * 49152;

    for (int ch = 0; ch < 6; ++ch) {
        __syncthreads();
        const uint4* srcB = (const uint4*)&g_wH[ch * 16][0][0][0];
        uint4* dB = (uint4*)sB;
        #pragma unroll
        for (int i = 0; i < 16; ++i) dB[t + i * 256] = srcB[t + i * 256];
        __syncthreads();
        float acc[2][4][4];
        gemm1h(sA, sB, mw, nwp, lane, acc);
        float sc = (ch < 2) ? QSCALE : 1.0f;
        #pragma unroll
        for (int m = 0; m < 2; ++m) {
            int row = (2 * mw + m) * 16 + (lane >> 2);
            #pragma unroll
            for (int nt = 0; nt < 4; ++nt) {
                int col = ch * 128 + (nwp * 4 + nt) * 8 + (lane & 3) * 2;
                *(__half2*)(dst + row * 768 + col) =
                    __floats2half2_rn(acc[m][nt][0] * sc, acc[m][nt][1] * sc);
                *(__half2*)(dst + (row + 8) * 768 + col) =
                    __floats2half2_rn(acc[m][nt][2] * sc, acc[m][nt][3] * sc);
            }
        }
    }
}

// ---------------- k2: attention (fp32 SIMT, stride-68 proven layout) ----------------
__global__ void __launch_bounds__(512, 2)
k2_attn(const float* __restrict__ pos) {
    extern __shared__ float sf[];
    float* qT = sf;               // [64 c][68]
    float* kT = sf + 4352;
    float* vbuf = sf + 8704;      // [64 j][64 c]
    float* P2 = sf + 12800;       // [2][64][68]
    const int t = threadIdx.x, win = blockIdx.x;
    const __half* src = g_qkv + (size_t)win * 49152;
    float* aout = g_ao + (size_t)win * 16384;
    const int sh = t >> 8, sidx = t & 255;
    const int sig = sidx >> 3, sjg = sidx & 7, aig = sidx >> 2, adg = sidx & 3;

    for (int hb = 0; hb < 4; ++hb) {
        #pragma unroll
        for (int rep = 0; rep < 2; ++rep) {
            int task = t + rep * 512, row = task >> 4, c4 = task & 15;
            const __half* s = src + row * 768 + hb * 64 + c4 * 4;
            uint2 qw = *(const uint2*)(s);
            uint2 kw = *(const uint2*)(s + 256);
            uint2 vw = *(const uint2*)(s + 512);
            float2 qa = __half22float2(*(__half2*)&qw.x), qb = __half22float2(*(__half2*)&qw.y);
            float2 ka = __half22float2(*(__half2*)&kw.x), kb = __half22float2(*(__half2*)&kw.y);
            float2 va = __half22float2(*(__half2*)&vw.x), vb2 = __half22float2(*(__half2*)&vw.y);
            int c = c4 * 4;
            qT[c*68+row]=qa.x; qT[(c+1)*68+row]=qa.y; qT[(c+2)*68+row]=qb.x; qT[(c+3)*68+row]=qb.y;
            kT[c*68+row]=ka.x; kT[(c+1)*68+row]=ka.y; kT[(c+2)*68+row]=kb.x; kT[(c+3)*68+row]=kb.y;
            *(float4*)(vbuf + row * 64 + c) = make_float4(va.x, va.y, vb2.x, vb2.y);
        }
        __syncthreads();
        {   // sim + softmax
            const int hq = sh * 32;
            ull s0[4] = {0,0,0,0}, s1[4] = {0,0,0,0};
            #pragma unroll 4
            for (int d = 0; d < 32; ++d) {
                float2 qv = *(const float2*)(qT + (hq + d) * 68 + sig * 2);
                ull q0 = pk(qv.x, qv.x), q1 = pk(qv.y, qv.y);
                const float* kr = kT + (hq + d) * 68 + sjg * 8;
                ulonglong2 ka = *(const ulonglong2*)(kr);
                ulonglong2 kb = *(const ulonglong2*)(kr + 4);
                s0[0]=fma2(q0,ka.x,s0[0]); s1[0]=fma2(q1,ka.x,s1[0]);
                s0[1]=fma2(q0,ka.y,s0[1]); s1[1]=fma2(q1,ka.y,s1[1]);
                s0[2]=fma2(q0,kb.x,s0[2]); s1[2]=fma2(q1,kb.x,s1[2]);
                s0[3]=fma2(q0,kb.y,s0[3]); s1[3]=fma2(q1,kb.y,s1[3]);
            }
            const int i0 = sig * 2, hcur = hb * 2 + sh;
            const float* pp = pos + hcur * 4096 + i0 * 64 + sjg * 8;
            float sv0[8], sv1[8];
            #pragma unroll
            for (int p = 0; p < 4; ++p) {
                float2 f0 = upk(s0[p]); sv0[p*2]=f0.x; sv0[p*2+1]=f0.y;
                float2 f1 = upk(s1[p]); sv1[p*2]=f1.x; sv1[p*2+1]=f1.y;
            }
            #pragma unroll
            for (int jj = 0; jj < 8; ++jj) { sv0[jj] += __ldg(pp + jj); sv1[jj] += __ldg(pp + 64 + jj); }
            float m0 = sv0[0], m1 = sv1[0];
            #pragma unroll
            for (int jj = 1; jj < 8; ++jj) { m0 = fmaxf(m0, sv0[jj]); m1 = fmaxf(m1, sv1[jj]); }
            #pragma unroll
            for (int o = 1; o < 8; o <<= 1) {
                m0 = fmaxf(m0, __shfl_xor_sync(0xffffffffu, m0, o));
                m1 = fmaxf(m1, __shfl_xor_sync(0xffffffffu, m1, o));
            }
            float su0 = 0.f, su1 = 0.f;
            #pragma unroll
            for (int jj = 0; jj < 8; ++jj) {
                sv0[jj] = __expf(sv0[jj] - m0); su0 += sv0[jj];
                sv1[jj] = __expf(sv1[jj] - m1); su1 += sv1[jj];
            }
            #pragma unroll
            for (int o = 1; o < 8; o <<= 1) {
                su0 += __shfl_xor_sync(0xffffffffu, su0, o);
                su1 += __shfl_xor_sync(0xffffffffu, su1, o);
            }
            float inv0 = 1.f / su0, inv1 = 1.f / su1;
            float* pr = P2 + sh * 4352 + i0 * 68 + sjg * 8;
            *(float4*)(pr)      = make_float4(sv0[0]*inv0, sv0[1]*inv0, sv0[2]*inv0, sv0[3]*inv0);
            *(float4*)(pr+4)    = make_float4(sv0[4]*inv0, sv0[5]*inv0, sv0[6]*inv0, sv0[7]*inv0);
            *(float4*)(pr+68)   = make_float4(sv1[0]*inv1, sv1[1]*inv1, sv1[2]*inv1, sv1[3]*inv1);
            *(float4*)(pr+68+4) = make_float4(sv1[4]*inv1, sv1[5]*inv1, sv1[6]*inv1, sv1[7]*inv1);
        }
        __syncthreads();
        {   // av
            ull o[4] = {0,0,0,0};
            const float* pr = P2 + sh * 4352 + aig * 68;
            const float* vp = vbuf + sh * 32 + adg * 8;
            #pragma unroll 4
            for (int j = 0; j < 64; ++j) {
                float p = pr[j]; ull pb = pk(p, p);
                ulonglong2 va = *(const ulonglong2*)(vp + j * 64);
                ulonglong2 vb2 = *(const ulonglong2*)(vp + j * 64 + 4);
                o[0]=fma2(pb,va.x,o[0]); o[1]=fma2(pb,va.y,o[1]);
                o[2]=fma2(pb,vb2.x,o[2]); o[3]=fma2(pb,vb2.y,o[3]);
            }
            int dbase = (hb * 2 + sh) * 32 + adg * 8;
            float2 f0=upk(o[0]), f1=upk(o[1]), f2=upk(o[2]), f3=upk(o[3]);
            *(float4*)(aout + aig * 256 + dbase)     = make_float4(f0.x, f0.y, f1.x, f1.y);
            *(float4*)(aout + aig * 256 + dbase + 4) = make_float4(f2.x, f2.y, f3.x, f3.y);
        }
        __syncthreads();
    }
}

// ---------------- k3: projection (fp16 1-pass, M=64, 8 warps m32n32, occ 2) ----------------
#define SMEM_K3 98304
__global__ void __launch_bounds__(256, 2)
k3_proj(const float* __restrict__ bp, float* __restrict__ out) {
    extern __shared__ uint32_t sm[];
    uint32_t* sA = sm;
    uint32_t* sB = sm + 8192;
    const int t = threadIdx.x, win = blockIdx.x;
    const float* ao = g_ao + (size_t)win * 16384;

    #pragma unroll
    for (int rep = 0; rep < 16; ++rep) {
        int task = t + rep * 256;
        int r = task >> 6, k4 = task & 63;
        float4 v = *(const float4*)(ao + r * 256 + k4 * 4);
        stageA1h(sA, r, k4, v);
    }

    const int w = t >> 5, lane = t & 31, mw = w >> 2, nwp = w & 3;
    const int b = win >> 10, nh = (win >> 5) & 31, nww = win & 31;
    float* obase = out + (((size_t)(b * 256 + nh * 8) * 256 + nww * 8) << 8);

    for (int ch = 0; ch < 2; ++ch) {
        __syncthreads();
        const uint4* srcB = (const uint4*)&g_wH[96 + ch * 16][0][0][0];
        uint4* dB = (uint4*)sB;
        #pragma unroll
        for (int i = 0; i < 16; ++i) dB[t + i * 256] = srcB[t + i * 256];
        __syncthreads();
        float acc[2][4][4];
        gemm1h(sA, sB, mw, nwp, lane, acc);
        #pragma unroll
        for (int m = 0; m < 2; ++m) {
            int row = (2 * mw + m) * 16 + (lane >> 2);
            #pragma unroll
            for (int nt = 0; nt < 4; ++nt) {
                int c = ch * 128 + (nwp * 4 + nt) * 8 + (lane & 3) * 2;
                float2 bias = *(const float2*)(bp + c);
                int r0 = row, r1 = row + 8;
                *(float2*)(obase + (r0 >> 3) * 65536 + (r0 & 7) * 256 + c) =
                    make_float2(acc[m][nt][0] + bias.x, acc[m][nt][1] + bias.y);
                *(float2*)(obase + (r1 >> 3) * 65536 + (r1 & 7) * 256 + c) =
                    make_float2(acc[m][nt][2] + bias.x, acc[m][nt][3] + bias.y);
            }
        }
    }
}

extern "C" void kernel_launch(void* const* d_in, const int* in_sizes, int n_in,
                              void* d_out, int out_size)
{
    const float* x   = (const float*)d_in[0];
    const float* Wq  = (const float*)d_in[1];
    const float* Wkv = (const float*)d_in[2];
    const float* pos = (const float*)d_in[3];
    const float* Wp  = (const float*)d_in[4];
    const float* bp  = (const float*)d_in[5];
    float* out = (float*)d_out;

    cudaFuncSetAttribute(k1_qkv,  cudaFuncAttributeMaxDynamicSharedMemorySize, SMEM_K1);
    cudaFuncSetAttribute(k2_attn, cudaFuncAttributeMaxDynamicSharedMemorySize, 86016);
    cudaFuncSetAttribute(k3_proj, cudaFuncAttributeMaxDynamicSharedMemorySize, SMEM_K3);

    k0_prep<<<256, 512>>>(Wq, Wkv, Wp);
    k1_qkv<<<4096, 256, SMEM_K1>>>(x);
    k2_attn<<<4096, 512, 86016>>>(pos);
    k3_proj<<<4096, 256, SMEM_K3>>>(bp, out);
}